// round 9
// baseline (speedup 1.0000x reference)
#include <cuda_runtime.h>
#include <cstdint>

#define T_LEN 2048
#define BATCH 8
#define EMBED 1024
#define NHEADS 16
#define HDIM 64
#define BH 128            // BATCH * NHEADS
#define MROWS 16384       // T_LEN * BATCH
#define NQKV 3072         // 3 * EMBED
#define QK_LD 65
#define S_LD 129

#define BK 32
#define TLD 36            // smem leading dim (floats) for A/B tiles
#define STAGES 3
#define TILE_FLOATS (128 * TLD)
#define GEMM_SMEM (STAGES * 2 * TILE_FLOATS * 4)   // 110592 B; x2 CTAs = 221KB/SM

// Scratch (allowed: __device__ globals, no dynamic allocation)
__device__ float g_qkv[(size_t)MROWS * NQKV];    // [T*B, 3E]
__device__ float g_ws[(size_t)MROWS * EMBED];    // [B, T, E] (tf32-rounded)
__device__ float g_qr[(size_t)MROWS * EMBED];    // query, tf32-rounded
__device__ float g_wqkv[(size_t)NQKV * EMBED];   // w_qkv, tf32-rounded
__device__ float g_wout[(size_t)EMBED * EMBED];  // w_out, tf32-rounded

__device__ __forceinline__ float tf32r(float x) {
    uint32_t u;
    asm("cvt.rna.tf32.f32 %0, %1;\n" : "=r"(u) : "f"(x));
    return __uint_as_float(u);
}

// ---------------------------------------------------------------------------
// Elementwise tf32 rounding: y = round_tf32(x), float4-vectorized.
// ---------------------------------------------------------------------------
__global__ __launch_bounds__(256) void round_tf32_kernel(
    const float* __restrict__ x, float* __restrict__ y, int n4)
{
    int i = blockIdx.x * blockDim.x + threadIdx.x;
    if (i < n4) {
        float4 v = ((const float4*)x)[i];
        v.x = tf32r(v.x); v.y = tf32r(v.y);
        v.z = tf32r(v.z); v.w = tf32r(v.w);
        ((float4*)y)[i] = v;
    }
}

// ---------------------------------------------------------------------------
// tf32 tensor-core GEMM: C[m][n] = sum_k A[m][k]*B[n][k] + bias[n]
// A and B MUST already be tf32-rounded (no cvt in the mainloop).
// 128x128 tile, BK=32, 256 threads, 8 warps (2x4), warp tile 64x32.
// 3-stage cp.async pipeline with wait_group(1): the tile consumed at
// iteration kt was issued at kt-2, so ~2 tiles of mma work hide each load.
// __launch_bounds__(256,2) + 110.6KB smem -> 2 CTAs/SM (221KB of 228KB).
// One __syncthreads per iteration: the stage overwritten by the prefetch
// was computed in the PREVIOUS iteration, separated by the top barrier.
// ---------------------------------------------------------------------------
__global__ __launch_bounds__(256, 2) void gemm_tf32_kernel(
    const float* __restrict__ A, const float* __restrict__ B,
    const float* __restrict__ bias, float* __restrict__ C,
    int N, int K)
{
    extern __shared__ float sm[];
    const int tid  = threadIdx.x;
    const int lane = tid & 31;
    const int warp = tid >> 5;
    const int wm   = warp >> 2;        // 0..1
    const int wn   = warp & 3;         // 0..3
    const int bm   = blockIdx.y << 7;
    const int bn   = blockIdx.x << 7;

    const int lrow = tid >> 3;         // 0..31
    const int lkc  = tid & 7;          // 0..7 (float4 chunks)
    const float* gA = A + (size_t)(bm + lrow) * K + lkc * 4;
    const float* gB = B + (size_t)(bn + lrow) * K + lkc * 4;

    // Precomputed ldmatrix shared coords (loop-invariant parts)
    const int a_row = wm * 64 + (lane & 15);          // + mf*16
    const int a_kof = (lane >> 4) * 4;
    const int b_row = wn * 32 + (lane & 7) + ((lane >> 4) << 3);  // + bi*16
    const int b_kof = ((lane >> 3) & 1) * 4;

    float c[4][4][4];
#pragma unroll
    for (int mf = 0; mf < 4; mf++)
#pragma unroll
        for (int nf = 0; nf < 4; nf++)
#pragma unroll
            for (int r = 0; r < 4; r++) c[mf][nf][r] = 0.0f;

    const int ntiles = K >> 5;

#define LOAD_TILE(s, k0) do {                                                  \
    float* As_ = sm + (s) * (2 * TILE_FLOATS);                                 \
    float* Bs_ = As_ + TILE_FLOATS;                                            \
    _Pragma("unroll")                                                          \
    for (int i_ = 0; i_ < 4; i_++) {                                           \
        uint32_t sa_ = (uint32_t)__cvta_generic_to_shared(                     \
            As_ + (lrow + i_ * 32) * TLD + lkc * 4);                           \
        asm volatile("cp.async.cg.shared.global [%0], [%1], 16;\n"             \
                     :: "r"(sa_), "l"(gA + (size_t)(i_ * 32) * K + (k0)));     \
        uint32_t sb_ = (uint32_t)__cvta_generic_to_shared(                     \
            Bs_ + (lrow + i_ * 32) * TLD + lkc * 4);                           \
        asm volatile("cp.async.cg.shared.global [%0], [%1], 16;\n"             \
                     :: "r"(sb_), "l"(gB + (size_t)(i_ * 32) * K + (k0)));     \
    }                                                                          \
} while (0)

    // prologue: fill stages 0 .. STAGES-2 (tiles 0,1)
#pragma unroll
    for (int s = 0; s < STAGES - 1; s++) {
        LOAD_TILE(s, s * BK);
        asm volatile("cp.async.commit_group;\n");
    }

    for (int kt = 0; kt < ntiles; kt++) {
        // tile kt arrived (allow 1 in-flight group = tile kt+1)
        asm volatile("cp.async.wait_group %0;\n" :: "n"(STAGES - 2));
        __syncthreads();

        // prefetch tile kt+2 into the stage consumed at iteration kt-1
        int pf = kt + STAGES - 1;
        if (pf < ntiles) LOAD_TILE(pf % STAGES, pf * BK);
        asm volatile("cp.async.commit_group;\n");

        const float* As = sm + (kt % STAGES) * (2 * TILE_FLOATS);
        const float* Bs = As + TILE_FLOATS;

#pragma unroll
        for (int k8 = 0; k8 < 4; k8++) {
            uint32_t afr[4][4];
#pragma unroll
            for (int mf = 0; mf < 4; mf++) {
                uint32_t addr = (uint32_t)__cvta_generic_to_shared(
                    As + (a_row + mf * 16) * TLD + k8 * 8 + a_kof);
                asm volatile(
                    "ldmatrix.sync.aligned.m8n8.x4.b16 {%0,%1,%2,%3}, [%4];\n"
                    : "=r"(afr[mf][0]), "=r"(afr[mf][1]),
                      "=r"(afr[mf][2]), "=r"(afr[mf][3])
                    : "r"(addr));
            }
            uint32_t bfr[4][2];
#pragma unroll
            for (int bi = 0; bi < 2; bi++) {
                uint32_t addr = (uint32_t)__cvta_generic_to_shared(
                    Bs + (b_row + bi * 16) * TLD + k8 * 8 + b_kof);
                asm volatile(
                    "ldmatrix.sync.aligned.m8n8.x4.b16 {%0,%1,%2,%3}, [%4];\n"
                    : "=r"(bfr[2 * bi][0]),     "=r"(bfr[2 * bi][1]),
                      "=r"(bfr[2 * bi + 1][0]), "=r"(bfr[2 * bi + 1][1])
                    : "r"(addr));
            }
#pragma unroll
            for (int mf = 0; mf < 4; mf++)
#pragma unroll
                for (int nf = 0; nf < 4; nf++) {
                    asm volatile(
                        "mma.sync.aligned.m16n8k8.row.col.f32.tf32.tf32.f32 "
                        "{%0,%1,%2,%3}, {%4,%5,%6,%7}, {%8,%9}, {%0,%1,%2,%3};\n"
                        : "+f"(c[mf][nf][0]), "+f"(c[mf][nf][1]),
                          "+f"(c[mf][nf][2]), "+f"(c[mf][nf][3])
                        : "r"(afr[mf][0]), "r"(afr[mf][1]),
                          "r"(afr[mf][2]), "r"(afr[mf][3]),
                          "r"(bfr[nf][0]), "r"(bfr[nf][1]));
                }
        }
    }

    // epilogue
#pragma unroll
    for (int mf = 0; mf < 4; mf++) {
        int r0 = bm + wm * 64 + mf * 16 + (lane >> 2);
#pragma unroll
        for (int nf = 0; nf < 4; nf++) {
            int col = bn + wn * 32 + nf * 8 + ((lane & 3) << 1);
            float2 bv = *(const float2*)(bias + col);
            float2 o0 = make_float2(c[mf][nf][0] + bv.x, c[mf][nf][1] + bv.y);
            float2 o1 = make_float2(c[mf][nf][2] + bv.x, c[mf][nf][3] + bv.y);
            *(float2*)(C + (size_t)r0 * N + col) = o0;
            *(float2*)(C + (size_t)(r0 + 8) * N + col) = o1;
        }
    }
#undef LOAD_TILE
}

// ---------------------------------------------------------------------------
// Per-t attention: one block per t (2048 blocks, 256 threads). fp32 exact.
// S[i][j] = (q_raw[i].k_raw[j]) * invq[i] * invk[j] / 8, softmax, P@V.
// Output tf32-rounded at store (consumed by the tf32 out-GEMM).
// ---------------------------------------------------------------------------
__global__ __launch_bounds__(256) void attn_kernel()
{
    extern __shared__ float fsm[];
    float* qs   = fsm;                     // 128 x 65
    float* ks   = qs + BH * QK_LD;         // 128 x 65
    float* vs   = ks + BH * QK_LD;         // 128 x 65
    float* Ss   = vs + BH * QK_LD;         // 128 x 129
    float* invq = Ss + BH * S_LD;          // 128
    float* invk = invq + BH;               // 128

    const int t = blockIdx.x;
    const int tid = threadIdx.x;

    for (int idx = tid; idx < BH * (HDIM / 4); idx += 256) {
        int a  = idx >> 4;
        int d4 = (idx & 15) << 2;
        int b = a >> 4, h = a & 15;
        const float* base = g_qkv + (size_t)(t * BATCH + b) * NQKV + h * HDIM + d4;
        float4 qv = *(const float4*)(base);
        float4 kv = *(const float4*)(base + EMBED);
        float4 vv = *(const float4*)(base + 2 * EMBED);
        float* qd = qs + a * QK_LD + d4;
        qd[0] = qv.x; qd[1] = qv.y; qd[2] = qv.z; qd[3] = qv.w;
        float* kd = ks + a * QK_LD + d4;
        kd[0] = kv.x; kd[1] = kv.y; kd[2] = kv.z; kd[3] = kv.w;
        float* vd = vs + a * QK_LD + d4;
        vd[0] = vv.x; vd[1] = vv.y; vd[2] = vv.z; vd[3] = vv.w;
    }
    __syncthreads();

    if (tid < BH) {
        const float* r = qs + tid * QK_LD;
        float s = 0.0f;
#pragma unroll
        for (int d = 0; d < HDIM; d++) s = fmaf(r[d], r[d], s);
        invq[tid] = rsqrtf(s);
    } else {
        const float* r = ks + (tid - BH) * QK_LD;
        float s = 0.0f;
#pragma unroll
        for (int d = 0; d < HDIM; d++) s = fmaf(r[d], r[d], s);
        invk[tid - BH] = rsqrtf(s);
    }
    __syncthreads();

    const int tx = tid & 15, ty = tid >> 4;

    {
        float acc[8][8];
#pragma unroll
        for (int i = 0; i < 8; i++)
#pragma unroll
            for (int j = 0; j < 8; j++) acc[i][j] = 0.0f;

#pragma unroll 8
        for (int k = 0; k < HDIM; k++) {
            float a_frag[8], b_frag[8];
#pragma unroll
            for (int i = 0; i < 8; i++) a_frag[i] = qs[((ty << 3) + i) * QK_LD + k];
#pragma unroll
            for (int j = 0; j < 8; j++) b_frag[j] = ks[((tx << 3) + j) * QK_LD + k];
#pragma unroll
            for (int i = 0; i < 8; i++)
#pragma unroll
                for (int j = 0; j < 8; j++)
                    acc[i][j] = fmaf(a_frag[i], b_frag[j], acc[i][j]);
        }
#pragma unroll
        for (int i = 0; i < 8; i++) {
            float si = invq[(ty << 3) + i] * 0.125f;
            float* srow = Ss + ((ty << 3) + i) * S_LD + (tx << 3);
#pragma unroll
            for (int j = 0; j < 8; j++)
                srow[j] = acc[i][j] * si * invk[(tx << 3) + j];
        }
    }
    __syncthreads();

    {
        const int warp = tid >> 5, lane = tid & 31;
        for (int r = warp * 16; r < warp * 16 + 16; r++) {
            float* row = Ss + r * S_LD;
            float v0 = row[lane], v1 = row[lane + 32];
            float v2 = row[lane + 64], v3 = row[lane + 96];
            float m = fmaxf(fmaxf(v0, v1), fmaxf(v2, v3));
#pragma unroll
            for (int o = 16; o > 0; o >>= 1)
                m = fmaxf(m, __shfl_xor_sync(0xffffffffu, m, o));
            v0 = __expf(v0 - m); v1 = __expf(v1 - m);
            v2 = __expf(v2 - m); v3 = __expf(v3 - m);
            float s = v0 + v1 + v2 + v3;
#pragma unroll
            for (int o = 16; o > 0; o >>= 1)
                s += __shfl_xor_sync(0xffffffffu, s, o);
            float inv = 1.0f / s;
            row[lane] = v0 * inv; row[lane + 32] = v1 * inv;
            row[lane + 64] = v2 * inv; row[lane + 96] = v3 * inv;
        }
    }
    __syncthreads();

    {
        float o[8][4];
#pragma unroll
        for (int i = 0; i < 8; i++)
#pragma unroll
            for (int c = 0; c < 4; c++) o[i][c] = 0.0f;

#pragma unroll 4
        for (int j = 0; j < BH; j++) {
            const float* vrow = vs + j * QK_LD + (tx << 2);
            float vv0 = vrow[0], vv1 = vrow[1], vv2 = vrow[2], vv3 = vrow[3];
#pragma unroll
            for (int i = 0; i < 8; i++) {
                float p = Ss[((ty << 3) + i) * S_LD + j];
                o[i][0] = fmaf(p, vv0, o[i][0]);
                o[i][1] = fmaf(p, vv1, o[i][1]);
                o[i][2] = fmaf(p, vv2, o[i][2]);
                o[i][3] = fmaf(p, vv3, o[i][3]);
            }
        }
#pragma unroll
        for (int i = 0; i < 8; i++) {
            int a = (ty << 3) + i;
            int b = a >> 4, h = a & 15;
            float* dst = g_ws + ((size_t)b * T_LEN + t) * EMBED + h * HDIM + (tx << 2);
            float4 ov = make_float4(tf32r(o[i][0]), tf32r(o[i][1]),
                                    tf32r(o[i][2]), tf32r(o[i][3]));
            *(float4*)dst = ov;
        }
    }
}

// ---------------------------------------------------------------------------
extern "C" void kernel_launch(void* const* d_in, const int* in_sizes, int n_in,
                              void* d_out, int out_size)
{
    const float* query = (const float*)d_in[0];
    // d_in[1] = key, d_in[2] = value: unused by the reference math
    const float* w_qkv = (const float*)d_in[3];
    const float* b_qkv = (const float*)d_in[4];
    const float* w_out = (const float*)d_in[5];
    const float* b_out = (const float*)d_in[6];
    float* out = (float*)d_out;

    const int attn_smem = (3 * BH * QK_LD + BH * S_LD + 2 * BH) * (int)sizeof(float);
    cudaFuncSetAttribute(attn_kernel,
                         cudaFuncAttributeMaxDynamicSharedMemorySize, attn_smem);
    cudaFuncSetAttribute(gemm_tf32_kernel,
                         cudaFuncAttributeMaxDynamicSharedMemorySize, GEMM_SMEM);

    float *qkv_ptr, *ws_ptr, *qr_ptr, *wqkv_ptr, *wout_ptr;
    cudaGetSymbolAddress((void**)&qkv_ptr, g_qkv);
    cudaGetSymbolAddress((void**)&ws_ptr, g_ws);
    cudaGetSymbolAddress((void**)&qr_ptr, g_qr);
    cudaGetSymbolAddress((void**)&wqkv_ptr, g_wqkv);
    cudaGetSymbolAddress((void**)&wout_ptr, g_wout);

    // Pre-round all tf32 GEMM operands (round-to-nearest on 19-bit tf32).
    {
        int n4q = (MROWS * EMBED) / 4;
        round_tf32_kernel<<<(n4q + 255) / 256, 256>>>(query, qr_ptr, n4q);
        int n4w = (NQKV * EMBED) / 4;
        round_tf32_kernel<<<(n4w + 255) / 256, 256>>>(w_qkv, wqkv_ptr, n4w);
        int n4o = (EMBED * EMBED) / 4;
        round_tf32_kernel<<<(n4o + 255) / 256, 256>>>(w_out, wout_ptr, n4o);
    }

    // QKV GEMM: [16384,1024] @ [3072,1024]^T -> g_qkv
    gemm_tf32_kernel<<<dim3(NQKV / 128, MROWS / 128), 256, GEMM_SMEM>>>(
        qr_ptr, wqkv_ptr, b_qkv, qkv_ptr, NQKV, EMBED);
    // fused per-t attention -> g_ws [B,T,E] (tf32-rounded)
    attn_kernel<<<T_LEN, 256, attn_smem>>>();
    // out GEMM: [16384,1024] @ [1024,1024]^T -> out
    gemm_tf32_kernel<<<dim3(EMBED / 128, MROWS / 128), 256, GEMM_SMEM>>>(
        ws_ptr, wout_ptr, b_out, out, EMBED, EMBED);
}

// round 11
// speedup vs baseline: 2.2588x; 2.2588x over previous
#include <cuda_runtime.h>
#include <cuda_fp16.h>
#include <cstdint>

#define T_LEN 2048
#define BATCH 8
#define EMBED 1024
#define NHEADS 16
#define HDIM 64
#define BH 128            // BATCH * NHEADS
#define MROWS 16384       // T_LEN * BATCH
#define NQKV 3072         // 3 * EMBED
#define QK_LD 65
#define S_LD 129

#define BK 64             // k halves per tile (128B rows)
#define TLD 72            // smem leading dim (halves): 64 + 8 pad, conflict-free
#define STAGES 3
#define TILEH (128 * TLD) // halves per operand tile
#define GEMM_SMEM (STAGES * 2 * TILEH * 2)   // 110592 B; x2 CTAs = 221KB/SM

// Scratch (allowed: __device__ globals, no dynamic allocation)
__device__ float  g_qkv[(size_t)MROWS * NQKV];    // [T*B, 3E] fp32
__device__ __half g_ws[(size_t)MROWS * EMBED];    // [B, T, E] fp16
__device__ __half g_qh[(size_t)MROWS * EMBED];    // query fp16
__device__ __half g_wqkv[(size_t)NQKV * EMBED];   // w_qkv fp16
__device__ __half g_wout[(size_t)EMBED * EMBED];  // w_out fp16

// ---------------------------------------------------------------------------
// Elementwise fp32 -> fp16 conversion, float4-vectorized.
// ---------------------------------------------------------------------------
__global__ __launch_bounds__(256) void to_half_kernel(
    const float* __restrict__ x, __half* __restrict__ y, int n4)
{
    int i = blockIdx.x * blockDim.x + threadIdx.x;
    if (i < n4) {
        float4 v = ((const float4*)x)[i];
        __half2* y2 = (__half2*)y;
        y2[2 * i]     = __floats2half2_rn(v.x, v.y);
        y2[2 * i + 1] = __floats2half2_rn(v.z, v.w);
    }
}

// ---------------------------------------------------------------------------
// fp16 tensor-core GEMM (fp32 accumulate): C[m][n] = sum_k A[m][k]*B[n][k]+bias[n]
// 128x128 tile, BK=64 halves, 256 threads, 8 warps (2x4), warp tile 64x32.
// mma.m16n8k16.f32.f16.f16.f32; ldmatrix.x4.b16 for A and B fragments.
// 3-stage cp.async; __launch_bounds__(256,2) -> 2 CTAs/SM.
// M,N multiples of 128; K multiple of 64.
// ---------------------------------------------------------------------------
__global__ __launch_bounds__(256, 2) void gemm_f16_kernel(
    const __half* __restrict__ A, const __half* __restrict__ B,
    const float* __restrict__ bias, float* __restrict__ C,
    int N, int K)
{
    extern __shared__ __half smh[];
    const int tid  = threadIdx.x;
    const int lane = tid & 31;
    const int warp = tid >> 5;
    const int wm   = warp >> 2;        // 0..1
    const int wn   = warp & 3;         // 0..3
    const int bm   = blockIdx.y << 7;
    const int bn   = blockIdx.x << 7;

    // global loads: 128 rows x 8 chunks(16B) per operand; 4 rows-groups/thread
    const int lrow   = tid >> 3;       // 0..31
    const int lchunk = tid & 7;        // 0..7
    const __half* gA = A + (size_t)(bm + lrow) * K + lchunk * 8;
    const __half* gB = B + (size_t)(bn + lrow) * K + lchunk * 8;

    // ldmatrix coords (halves)
    const int a_row  = wm * 64 + (lane & 15);           // + mf*16
    const int a_koff = (lane >> 4) * 8;
    const int b_row  = wn * 32 + ((lane >> 4) & 1) * 8 + (lane & 7);  // + bi*16
    const int b_koff = ((lane >> 3) & 1) * 8;

    float c[4][4][4];
#pragma unroll
    for (int mf = 0; mf < 4; mf++)
#pragma unroll
        for (int nf = 0; nf < 4; nf++)
#pragma unroll
            for (int r = 0; r < 4; r++) c[mf][nf][r] = 0.0f;

    const int ntiles = K >> 6;         // K / 64

#define LOAD_TILE(s, k0) do {                                                  \
    __half* As_ = smh + (s) * (2 * TILEH);                                     \
    __half* Bs_ = As_ + TILEH;                                                 \
    _Pragma("unroll")                                                          \
    for (int i_ = 0; i_ < 4; i_++) {                                           \
        uint32_t sa_ = (uint32_t)__cvta_generic_to_shared(                     \
            As_ + (lrow + i_ * 32) * TLD + lchunk * 8);                        \
        asm volatile("cp.async.cg.shared.global [%0], [%1], 16;\n"             \
                     :: "r"(sa_), "l"(gA + (size_t)(i_ * 32) * K + (k0)));     \
        uint32_t sb_ = (uint32_t)__cvta_generic_to_shared(                     \
            Bs_ + (lrow + i_ * 32) * TLD + lchunk * 8);                        \
        asm volatile("cp.async.cg.shared.global [%0], [%1], 16;\n"             \
                     :: "r"(sb_), "l"(gB + (size_t)(i_ * 32) * K + (k0)));     \
    }                                                                          \
} while (0)

    // prologue: tiles 0 .. STAGES-2
#pragma unroll
    for (int s = 0; s < STAGES - 1; s++) {
        LOAD_TILE(s, s * BK);
        asm volatile("cp.async.commit_group;\n");
    }

    for (int kt = 0; kt < ntiles; kt++) {
        asm volatile("cp.async.wait_group %0;\n" :: "n"(STAGES - 2));
        __syncthreads();

        int pf = kt + STAGES - 1;
        if (pf < ntiles) LOAD_TILE(pf % STAGES, pf * BK);
        asm volatile("cp.async.commit_group;\n");

        const __half* As = smh + (kt % STAGES) * (2 * TILEH);
        const __half* Bs = As + TILEH;

#pragma unroll
        for (int ks = 0; ks < 4; ks++) {            // 4 x k16 per BK=64
            uint32_t afr[4][4];
#pragma unroll
            for (int mf = 0; mf < 4; mf++) {
                uint32_t addr = (uint32_t)__cvta_generic_to_shared(
                    As + (a_row + mf * 16) * TLD + ks * 16 + a_koff);
                asm volatile(
                    "ldmatrix.sync.aligned.m8n8.x4.b16 {%0,%1,%2,%3}, [%4];\n"
                    : "=r"(afr[mf][0]), "=r"(afr[mf][1]),
                      "=r"(afr[mf][2]), "=r"(afr[mf][3])
                    : "r"(addr));
            }
            uint32_t bfr[4][2];
#pragma unroll
            for (int bi = 0; bi < 2; bi++) {
                uint32_t addr = (uint32_t)__cvta_generic_to_shared(
                    Bs + (b_row + bi * 16) * TLD + ks * 16 + b_koff);
                asm volatile(
                    "ldmatrix.sync.aligned.m8n8.x4.b16 {%0,%1,%2,%3}, [%4];\n"
                    : "=r"(bfr[2 * bi][0]),     "=r"(bfr[2 * bi][1]),
                      "=r"(bfr[2 * bi + 1][0]), "=r"(bfr[2 * bi + 1][1])
                    : "r"(addr));
            }
#pragma unroll
            for (int mf = 0; mf < 4; mf++)
#pragma unroll
                for (int nf = 0; nf < 4; nf++) {
                    asm volatile(
                        "mma.sync.aligned.m16n8k16.row.col.f32.f16.f16.f32 "
                        "{%0,%1,%2,%3}, {%4,%5,%6,%7}, {%8,%9}, {%0,%1,%2,%3};\n"
                        : "+f"(c[mf][nf][0]), "+f"(c[mf][nf][1]),
                          "+f"(c[mf][nf][2]), "+f"(c[mf][nf][3])
                        : "r"(afr[mf][0]), "r"(afr[mf][1]),
                          "r"(afr[mf][2]), "r"(afr[mf][3]),
                          "r"(bfr[nf][0]), "r"(bfr[nf][1]));
                }
        }
    }

    // epilogue
#pragma unroll
    for (int mf = 0; mf < 4; mf++) {
        int r0 = bm + wm * 64 + mf * 16 + (lane >> 2);
#pragma unroll
        for (int nf = 0; nf < 4; nf++) {
            int col = bn + wn * 32 + nf * 8 + ((lane & 3) << 1);
            float2 bv = *(const float2*)(bias + col);
            float2 o0 = make_float2(c[mf][nf][0] + bv.x, c[mf][nf][1] + bv.y);
            float2 o1 = make_float2(c[mf][nf][2] + bv.x, c[mf][nf][3] + bv.y);
            *(float2*)(C + (size_t)r0 * N + col) = o0;
            *(float2*)(C + (size_t)(r0 + 8) * N + col) = o1;
        }
    }
#undef LOAD_TILE
}

// ---------------------------------------------------------------------------
// Per-t attention: one block per t (2048 blocks, 256 threads). fp32 exact.
// S[i][j] = (q_raw[i].k_raw[j]) * invq[i] * invk[j] / 8, softmax, P@V.
// Output stored as fp16 (consumed by the fp16 out-GEMM).
// ---------------------------------------------------------------------------
__global__ __launch_bounds__(256) void attn_kernel()
{
    extern __shared__ float fsm[];
    float* qs   = fsm;                     // 128 x 65
    float* ks   = qs + BH * QK_LD;         // 128 x 65
    float* vs   = ks + BH * QK_LD;         // 128 x 65
    float* Ss   = vs + BH * QK_LD;         // 128 x 129
    float* invq = Ss + BH * S_LD;          // 128
    float* invk = invq + BH;               // 128

    const int t = blockIdx.x;
    const int tid = threadIdx.x;

    for (int idx = tid; idx < BH * (HDIM / 4); idx += 256) {
        int a  = idx >> 4;
        int d4 = (idx & 15) << 2;
        int b = a >> 4, h = a & 15;
        const float* base = g_qkv + (size_t)(t * BATCH + b) * NQKV + h * HDIM + d4;
        float4 qv = *(const float4*)(base);
        float4 kv = *(const float4*)(base + EMBED);
        float4 vv = *(const float4*)(base + 2 * EMBED);
        float* qd = qs + a * QK_LD + d4;
        qd[0] = qv.x; qd[1] = qv.y; qd[2] = qv.z; qd[3] = qv.w;
        float* kd = ks + a * QK_LD + d4;
        kd[0] = kv.x; kd[1] = kv.y; kd[2] = kv.z; kd[3] = kv.w;
        float* vd = vs + a * QK_LD + d4;
        vd[0] = vv.x; vd[1] = vv.y; vd[2] = vv.z; vd[3] = vv.w;
    }
    __syncthreads();

    if (tid < BH) {
        const float* r = qs + tid * QK_LD;
        float s = 0.0f;
#pragma unroll
        for (int d = 0; d < HDIM; d++) s = fmaf(r[d], r[d], s);
        invq[tid] = rsqrtf(s);
    } else {
        const float* r = ks + (tid - BH) * QK_LD;
        float s = 0.0f;
#pragma unroll
        for (int d = 0; d < HDIM; d++) s = fmaf(r[d], r[d], s);
        invk[tid - BH] = rsqrtf(s);
    }
    __syncthreads();

    const int tx = tid & 15, ty = tid >> 4;

    {
        float acc[8][8];
#pragma unroll
        for (int i = 0; i < 8; i++)
#pragma unroll
            for (int j = 0; j < 8; j++) acc[i][j] = 0.0f;

#pragma unroll 8
        for (int k = 0; k < HDIM; k++) {
            float a_frag[8], b_frag[8];
#pragma unroll
            for (int i = 0; i < 8; i++) a_frag[i] = qs[((ty << 3) + i) * QK_LD + k];
#pragma unroll
            for (int j = 0; j < 8; j++) b_frag[j] = ks[((tx << 3) + j) * QK_LD + k];
#pragma unroll
            for (int i = 0; i < 8; i++)
#pragma unroll
                for (int j = 0; j < 8; j++)
                    acc[i][j] = fmaf(a_frag[i], b_frag[j], acc[i][j]);
        }
#pragma unroll
        for (int i = 0; i < 8; i++) {
            float si = invq[(ty << 3) + i] * 0.125f;
            float* srow = Ss + ((ty << 3) + i) * S_LD + (tx << 3);
#pragma unroll
            for (int j = 0; j < 8; j++)
                srow[j] = acc[i][j] * si * invk[(tx << 3) + j];
        }
    }
    __syncthreads();

    {
        const int warp = tid >> 5, lane = tid & 31;
        for (int r = warp * 16; r < warp * 16 + 16; r++) {
            float* row = Ss + r * S_LD;
            float v0 = row[lane], v1 = row[lane + 32];
            float v2 = row[lane + 64], v3 = row[lane + 96];
            float m = fmaxf(fmaxf(v0, v1), fmaxf(v2, v3));
#pragma unroll
            for (int o = 16; o > 0; o >>= 1)
                m = fmaxf(m, __shfl_xor_sync(0xffffffffu, m, o));
            v0 = __expf(v0 - m); v1 = __expf(v1 - m);
            v2 = __expf(v2 - m); v3 = __expf(v3 - m);
            float s = v0 + v1 + v2 + v3;
#pragma unroll
            for (int o = 16; o > 0; o >>= 1)
                s += __shfl_xor_sync(0xffffffffu, s, o);
            float inv = 1.0f / s;
            row[lane] = v0 * inv; row[lane + 32] = v1 * inv;
            row[lane + 64] = v2 * inv; row[lane + 96] = v3 * inv;
        }
    }
    __syncthreads();

    {
        float o[8][4];
#pragma unroll
        for (int i = 0; i < 8; i++)
#pragma unroll
            for (int c = 0; c < 4; c++) o[i][c] = 0.0f;

#pragma unroll 4
        for (int j = 0; j < BH; j++) {
            const float* vrow = vs + j * QK_LD + (tx << 2);
            float vv0 = vrow[0], vv1 = vrow[1], vv2 = vrow[2], vv3 = vrow[3];
#pragma unroll
            for (int i = 0; i < 8; i++) {
                float p = Ss[((ty << 3) + i) * S_LD + j];
                o[i][0] = fmaf(p, vv0, o[i][0]);
                o[i][1] = fmaf(p, vv1, o[i][1]);
                o[i][2] = fmaf(p, vv2, o[i][2]);
                o[i][3] = fmaf(p, vv3, o[i][3]);
            }
        }
#pragma unroll
        for (int i = 0; i < 8; i++) {
            int a = (ty << 3) + i;
            int b = a >> 4, h = a & 15;
            __half* dst = g_ws + ((size_t)b * T_LEN + t) * EMBED + h * HDIM + (tx << 2);
            *(__half2*)(dst)     = __floats2half2_rn(o[i][0], o[i][1]);
            *(__half2*)(dst + 2) = __floats2half2_rn(o[i][2], o[i][3]);
        }
    }
}

// ---------------------------------------------------------------------------
extern "C" void kernel_launch(void* const* d_in, const int* in_sizes, int n_in,
                              void* d_out, int out_size)
{
    const float* query = (const float*)d_in[0];
    // d_in[1] = key, d_in[2] = value: unused by the reference math
    const float* w_qkv = (const float*)d_in[3];
    const float* b_qkv = (const float*)d_in[4];
    const float* w_out = (const float*)d_in[5];
    const float* b_out = (const float*)d_in[6];
    float* out = (float*)d_out;

    const int attn_smem = (3 * BH * QK_LD + BH * S_LD + 2 * BH) * (int)sizeof(float);
    cudaFuncSetAttribute(attn_kernel,
                         cudaFuncAttributeMaxDynamicSharedMemorySize, attn_smem);
    cudaFuncSetAttribute(gemm_f16_kernel,
                         cudaFuncAttributeMaxDynamicSharedMemorySize, GEMM_SMEM);

    float* qkv_ptr;
    __half *ws_ptr, *qh_ptr, *wqkv_ptr, *wout_ptr;
    cudaGetSymbolAddress((void**)&qkv_ptr, g_qkv);
    cudaGetSymbolAddress((void**)&ws_ptr, g_ws);
    cudaGetSymbolAddress((void**)&qh_ptr, g_qh);
    cudaGetSymbolAddress((void**)&wqkv_ptr, g_wqkv);
    cudaGetSymbolAddress((void**)&wout_ptr, g_wout);

    // Convert fp16 GEMM operands (round-to-nearest).
    {
        int n4q = (MROWS * EMBED) / 4;
        to_half_kernel<<<(n4q + 255) / 256, 256>>>(query, qh_ptr, n4q);
        int n4w = (NQKV * EMBED) / 4;
        to_half_kernel<<<(n4w + 255) / 256, 256>>>(w_qkv, wqkv_ptr, n4w);
        int n4o = (EMBED * EMBED) / 4;
        to_half_kernel<<<(n4o + 255) / 256, 256>>>(w_out, wout_ptr, n4o);
    }

    // QKV GEMM: [16384,1024] @ [3072,1024]^T -> g_qkv (fp32)
    gemm_f16_kernel<<<dim3(NQKV / 128, MROWS / 128), 256, GEMM_SMEM>>>(
        qh_ptr, wqkv_ptr, b_qkv, qkv_ptr, NQKV, EMBED);
    // fused per-t attention -> g_ws [B,T,E] (fp16)
    attn_kernel<<<T_LEN, 256, attn_smem>>>();
    // out GEMM: [16384,1024] @ [1024,1024]^T -> out (fp32)
    gemm_f16_kernel<<<dim3(EMBED / 128, MROWS / 128), 256, GEMM_SMEM>>>(
        ws_ptr, wout_ptr, b_out, out, EMBED, EMBED);
}

// round 13
// speedup vs baseline: 2.8684x; 1.2699x over previous
#include <cuda_runtime.h>
#include <cuda_fp16.h>
#include <cstdint>

#define T_LEN 2048
#define BATCH 8
#define EMBED 1024
#define NHEADS 16
#define HDIM 64
#define BH 128            // BATCH * NHEADS
#define MROWS 16384       // T_LEN * BATCH
#define NQKV 3072         // 3 * EMBED
#define S_LD 129

#define BK 64             // k halves per tile (128B rows)
#define TLD 72            // smem leading dim (halves): 64 + 8 pad, conflict-free
#define STAGES 3
#define TILEH (128 * TLD) // halves per operand tile
#define GEMM_SMEM (STAGES * 2 * TILEH * 2)   // 110592 B; x2 CTAs = 221KB/SM

// attention smem layout (bytes)
#define QH_LD 72
#define VT_LD 136
#define PH_LD 136
#define OFF_SS   0
#define OFF_QH   (OFF_SS + BH * S_LD * 4)           // 66048
#define OFF_KH   (OFF_QH + BH * QH_LD * 2)          // 84480
#define OFF_VT   (OFF_KH + BH * QH_LD * 2)          // 102912
#define OFF_PH   (OFF_VT + HDIM * VT_LD * 2)        // 120320
#define OFF_IQ   (OFF_PH + BH * PH_LD * 2)          // 155136
#define OFF_IK   (OFF_IQ + BH * 4)
#define ATTN_SMEM (OFF_IK + BH * 4)                 // 156160

// Scratch (allowed: __device__ globals, no dynamic allocation)
__device__ float  g_qkv[(size_t)MROWS * NQKV];    // [T*B, 3E] fp32
__device__ __half g_ws[(size_t)MROWS * EMBED];    // [B, T, E] fp16
__device__ __half g_qh[(size_t)MROWS * EMBED];    // query fp16
__device__ __half g_wqkv[(size_t)NQKV * EMBED];   // w_qkv fp16
__device__ __half g_wout[(size_t)EMBED * EMBED];  // w_out fp16

#define LDM_X4(r0, r1, r2, r3, p) \
    asm volatile("ldmatrix.sync.aligned.m8n8.x4.b16 {%0,%1,%2,%3}, [%4];\n" \
                 : "=r"(r0), "=r"(r1), "=r"(r2), "=r"(r3) \
                 : "r"((uint32_t)__cvta_generic_to_shared(p)))

#define MMA_F16(c, af, b0, b1) \
    asm volatile("mma.sync.aligned.m16n8k16.row.col.f32.f16.f16.f32 " \
                 "{%0,%1,%2,%3}, {%4,%5,%6,%7}, {%8,%9}, {%0,%1,%2,%3};\n" \
                 : "+f"((c)[0]), "+f"((c)[1]), "+f"((c)[2]), "+f"((c)[3]) \
                 : "r"((af)[0]), "r"((af)[1]), "r"((af)[2]), "r"((af)[3]), \
                   "r"(b0), "r"(b1))

// ---------------------------------------------------------------------------
// Elementwise fp32 -> fp16 conversion, float4-vectorized.
// ---------------------------------------------------------------------------
__global__ __launch_bounds__(256) void to_half_kernel(
    const float* __restrict__ x, __half* __restrict__ y, int n4)
{
    int i = blockIdx.x * blockDim.x + threadIdx.x;
    if (i < n4) {
        float4 v = ((const float4*)x)[i];
        __half2* y2 = (__half2*)y;
        y2[2 * i]     = __floats2half2_rn(v.x, v.y);
        y2[2 * i + 1] = __floats2half2_rn(v.z, v.w);
    }
}

// ---------------------------------------------------------------------------
// fp16 tensor-core GEMM (fp32 accumulate): C[m][n] = sum_k A[m][k]*B[n][k]+bias[n]
// 128x128 tile, BK=64 halves, 256 threads, 8 warps (2x4), warp tile 64x32.
// ---------------------------------------------------------------------------
__global__ __launch_bounds__(256, 2) void gemm_f16_kernel(
    const __half* __restrict__ A, const __half* __restrict__ B,
    const float* __restrict__ bias, float* __restrict__ C,
    int N, int K)
{
    extern __shared__ __half smh[];
    const int tid  = threadIdx.x;
    const int lane = tid & 31;
    const int warp = tid >> 5;
    const int wm   = warp >> 2;
    const int wn   = warp & 3;
    const int bm   = blockIdx.y << 7;
    const int bn   = blockIdx.x << 7;

    const int lrow   = tid >> 3;
    const int lchunk = tid & 7;
    const __half* gA = A + (size_t)(bm + lrow) * K + lchunk * 8;
    const __half* gB = B + (size_t)(bn + lrow) * K + lchunk * 8;

    const int a_row  = wm * 64 + (lane & 15);
    const int a_koff = (lane >> 4) * 8;
    const int b_row  = wn * 32 + ((lane >> 4) & 1) * 8 + (lane & 7);
    const int b_koff = ((lane >> 3) & 1) * 8;

    float c[4][4][4];
#pragma unroll
    for (int mf = 0; mf < 4; mf++)
#pragma unroll
        for (int nf = 0; nf < 4; nf++)
#pragma unroll
            for (int r = 0; r < 4; r++) c[mf][nf][r] = 0.0f;

    const int ntiles = K >> 6;

#define LOAD_TILE(s, k0) do {                                                  \
    __half* As_ = smh + (s) * (2 * TILEH);                                     \
    __half* Bs_ = As_ + TILEH;                                                 \
    _Pragma("unroll")                                                          \
    for (int i_ = 0; i_ < 4; i_++) {                                           \
        uint32_t sa_ = (uint32_t)__cvta_generic_to_shared(                     \
            As_ + (lrow + i_ * 32) * TLD + lchunk * 8);                        \
        asm volatile("cp.async.cg.shared.global [%0], [%1], 16;\n"             \
                     :: "r"(sa_), "l"(gA + (size_t)(i_ * 32) * K + (k0)));     \
        uint32_t sb_ = (uint32_t)__cvta_generic_to_shared(                     \
            Bs_ + (lrow + i_ * 32) * TLD + lchunk * 8);                        \
        asm volatile("cp.async.cg.shared.global [%0], [%1], 16;\n"             \
                     :: "r"(sb_), "l"(gB + (size_t)(i_ * 32) * K + (k0)));     \
    }                                                                          \
} while (0)

#pragma unroll
    for (int s = 0; s < STAGES - 1; s++) {
        LOAD_TILE(s, s * BK);
        asm volatile("cp.async.commit_group;\n");
    }

    for (int kt = 0; kt < ntiles; kt++) {
        asm volatile("cp.async.wait_group %0;\n" :: "n"(STAGES - 2));
        __syncthreads();

        int pf = kt + STAGES - 1;
        if (pf < ntiles) LOAD_TILE(pf % STAGES, pf * BK);
        asm volatile("cp.async.commit_group;\n");

        const __half* As = smh + (kt % STAGES) * (2 * TILEH);
        const __half* Bs = As + TILEH;

#pragma unroll
        for (int ks = 0; ks < 4; ks++) {
            uint32_t afr[4][4];
#pragma unroll
            for (int mf = 0; mf < 4; mf++)
                LDM_X4(afr[mf][0], afr[mf][1], afr[mf][2], afr[mf][3],
                       As + (a_row + mf * 16) * TLD + ks * 16 + a_koff);
            uint32_t bfr[4][2];
#pragma unroll
            for (int bi = 0; bi < 2; bi++)
                LDM_X4(bfr[2 * bi][0], bfr[2 * bi][1],
                       bfr[2 * bi + 1][0], bfr[2 * bi + 1][1],
                       Bs + (b_row + bi * 16) * TLD + ks * 16 + b_koff);
#pragma unroll
            for (int mf = 0; mf < 4; mf++)
#pragma unroll
                for (int nf = 0; nf < 4; nf++)
                    MMA_F16(c[mf][nf], afr[mf], bfr[nf][0], bfr[nf][1]);
        }
    }

#pragma unroll
    for (int mf = 0; mf < 4; mf++) {
        int r0 = bm + wm * 64 + mf * 16 + (lane >> 2);
#pragma unroll
        for (int nf = 0; nf < 4; nf++) {
            int col = bn + wn * 32 + nf * 8 + ((lane & 3) << 1);
            float2 bv = *(const float2*)(bias + col);
            float2 o0 = make_float2(c[mf][nf][0] + bv.x, c[mf][nf][1] + bv.y);
            float2 o1 = make_float2(c[mf][nf][2] + bv.x, c[mf][nf][3] + bv.y);
            *(float2*)(C + (size_t)r0 * N + col) = o0;
            *(float2*)(C + (size_t)(r0 + 8) * N + col) = o1;
        }
    }
#undef LOAD_TILE
}

// ---------------------------------------------------------------------------
// Per-t tensor-core attention: one block per t (2048 blocks, 256 threads).
// q/k/v converted to fp16; S = (qh.kh)*invq*invk/8 (fp32 accum), fp32 softmax,
// P (fp16) @ V^T (fp16) with fp32 accum. Output fp16 to g_ws.
// ---------------------------------------------------------------------------
__global__ __launch_bounds__(256) void attn_kernel()
{
    extern __shared__ char smem[];
    float*  Ss   = (float*)(smem + OFF_SS);    // 128 x 129 fp32
    __half* qh   = (__half*)(smem + OFF_QH);   // 128 x 72
    __half* kh   = (__half*)(smem + OFF_KH);   // 128 x 72
    __half* vt   = (__half*)(smem + OFF_VT);   // 64 x 136 (transposed: [d][j])
    __half* ph   = (__half*)(smem + OFF_PH);   // 128 x 136
    float*  invq = (float*)(smem + OFF_IQ);    // 128
    float*  invk = (float*)(smem + OFF_IK);    // 128

    const int t = blockIdx.x;
    const int tid = threadIdx.x;
    const int lane = tid & 31;
    const int warp = tid >> 5;
    const int wm = warp >> 2;      // 0..1
    const int wn = warp & 3;       // 0..3

    // Load q,k,v (fp32) -> fp16 tiles; v stored transposed vt[d][j]
    for (int idx = tid; idx < BH * (HDIM / 4); idx += 256) {
        int a  = idx >> 4;                 // row 0..127
        int d4 = (idx & 15) << 2;          // 0,4,..,60
        int b = a >> 4, h = a & 15;
        const float* base = g_qkv + (size_t)(t * BATCH + b) * NQKV + h * HDIM + d4;
        float4 qv = *(const float4*)(base);
        float4 kv = *(const float4*)(base + EMBED);
        float4 vv = *(const float4*)(base + 2 * EMBED);
        __half2* qd = (__half2*)(qh + a * QH_LD + d4);
        qd[0] = __floats2half2_rn(qv.x, qv.y);
        qd[1] = __floats2half2_rn(qv.z, qv.w);
        __half2* kd = (__half2*)(kh + a * QH_LD + d4);
        kd[0] = __floats2half2_rn(kv.x, kv.y);
        kd[1] = __floats2half2_rn(kv.z, kv.w);
        vt[(d4 + 0) * VT_LD + a] = __float2half_rn(vv.x);
        vt[(d4 + 1) * VT_LD + a] = __float2half_rn(vv.y);
        vt[(d4 + 2) * VT_LD + a] = __float2half_rn(vv.z);
        vt[(d4 + 3) * VT_LD + a] = __float2half_rn(vv.w);
    }
    __syncthreads();

    // Row norms over the fp16 values (consistent cosine of rounded vectors)
    {
        const __half2* r = (const __half2*)((tid < BH ? qh : kh)
                            + (tid & 127) * QH_LD);
        float s = 0.0f;
#pragma unroll
        for (int d = 0; d < HDIM / 2; d++) {
            float2 f = __half22float2(r[d]);
            s = fmaf(f.x, f.x, fmaf(f.y, f.y, s));
        }
        float inv = rsqrtf(s);
        if (tid < BH) invq[tid] = inv; else invk[tid - BH] = inv;
    }
    __syncthreads();

    // S = qh @ kh^T (fp32 accum), scaled -> Ss
    {
        const int a_row  = wm * 64 + (lane & 15);
        const int a_koff = (lane >> 4) * 8;
        const int b_row  = wn * 32 + ((lane >> 4) & 1) * 8 + (lane & 7);
        const int b_koff = ((lane >> 3) & 1) * 8;

        float c[4][4][4];
#pragma unroll
        for (int mf = 0; mf < 4; mf++)
#pragma unroll
            for (int nf = 0; nf < 4; nf++)
#pragma unroll
                for (int r = 0; r < 4; r++) c[mf][nf][r] = 0.0f;

#pragma unroll
        for (int ks = 0; ks < 4; ks++) {           // K = 64 = 4 x 16
            uint32_t afr[4][4];
#pragma unroll
            for (int mf = 0; mf < 4; mf++)
                LDM_X4(afr[mf][0], afr[mf][1], afr[mf][2], afr[mf][3],
                       qh + (a_row + mf * 16) * QH_LD + ks * 16 + a_koff);
            uint32_t bfr[4][2];
#pragma unroll
            for (int bi = 0; bi < 2; bi++)
                LDM_X4(bfr[2 * bi][0], bfr[2 * bi][1],
                       bfr[2 * bi + 1][0], bfr[2 * bi + 1][1],
                       kh + (b_row + bi * 16) * QH_LD + ks * 16 + b_koff);
#pragma unroll
            for (int mf = 0; mf < 4; mf++)
#pragma unroll
                for (int nf = 0; nf < 4; nf++)
                    MMA_F16(c[mf][nf], afr[mf], bfr[nf][0], bfr[nf][1]);
        }

        // scale and write to Ss
#pragma unroll
        for (int mf = 0; mf < 4; mf++) {
            int r0 = wm * 64 + mf * 16 + (lane >> 2);
            float s0 = invq[r0] * 0.125f;
            float s1 = invq[r0 + 8] * 0.125f;
#pragma unroll
            for (int nf = 0; nf < 4; nf++) {
                int col = wn * 32 + nf * 8 + ((lane & 3) << 1);
                float k0 = invk[col], k1 = invk[col + 1];
                Ss[r0 * S_LD + col]           = c[mf][nf][0] * s0 * k0;
                Ss[r0 * S_LD + col + 1]       = c[mf][nf][1] * s0 * k1;
                Ss[(r0 + 8) * S_LD + col]     = c[mf][nf][2] * s1 * k0;
                Ss[(r0 + 8) * S_LD + col + 1] = c[mf][nf][3] * s1 * k1;
            }
        }
    }
    __syncthreads();

    // Softmax (fp32, exact); write P as fp16 into ph
    {
        for (int r = warp * 16; r < warp * 16 + 16; r++) {
            float* row = Ss + r * S_LD;
            __half* prow = ph + r * PH_LD;
            float v0 = row[lane], v1 = row[lane + 32];
            float v2 = row[lane + 64], v3 = row[lane + 96];
            float m = fmaxf(fmaxf(v0, v1), fmaxf(v2, v3));
#pragma unroll
            for (int o = 16; o > 0; o >>= 1)
                m = fmaxf(m, __shfl_xor_sync(0xffffffffu, m, o));
            v0 = __expf(v0 - m); v1 = __expf(v1 - m);
            v2 = __expf(v2 - m); v3 = __expf(v3 - m);
            float s = v0 + v1 + v2 + v3;
#pragma unroll
            for (int o = 16; o > 0; o >>= 1)
                s += __shfl_xor_sync(0xffffffffu, s, o);
            float inv = 1.0f / s;
            prow[lane]      = __float2half_rn(v0 * inv);
            prow[lane + 32] = __float2half_rn(v1 * inv);
            prow[lane + 64] = __float2half_rn(v2 * inv);
            prow[lane + 96] = __float2half_rn(v3 * inv);
        }
    }
    __syncthreads();

    // ws = P @ V : A = ph [128x128], B = vt [64 rows(d) x 128 k(j)]
    {
        const int a_row  = wm * 64 + (lane & 15);
        const int a_koff = (lane >> 4) * 8;
        const int b_row  = wn * 16 + ((lane >> 4) & 1) * 8 + (lane & 7);
        const int b_koff = ((lane >> 3) & 1) * 8;

        float o[4][2][4];
#pragma unroll
        for (int mf = 0; mf < 4; mf++)
#pragma unroll
            for (int nf = 0; nf < 2; nf++)
#pragma unroll
                for (int r = 0; r < 4; r++) o[mf][nf][r] = 0.0f;

#pragma unroll
        for (int ks = 0; ks < 8; ks++) {           // K = 128 = 8 x 16
            uint32_t afr[4][4];
#pragma unroll
            for (int mf = 0; mf < 4; mf++)
                LDM_X4(afr[mf][0], afr[mf][1], afr[mf][2], afr[mf][3],
                       ph + (a_row + mf * 16) * PH_LD + ks * 16 + a_koff);
            uint32_t bfr[2][2];
            LDM_X4(bfr[0][0], bfr[0][1], bfr[1][0], bfr[1][1],
                   vt + b_row * VT_LD + ks * 16 + b_koff);
#pragma unroll
            for (int mf = 0; mf < 4; mf++)
#pragma unroll
                for (int nf = 0; nf < 2; nf++)
                    MMA_F16(o[mf][nf], afr[mf], bfr[nf][0], bfr[nf][1]);
        }

        // store fp16 to g_ws [B, T, E]
#pragma unroll
        for (int mf = 0; mf < 4; mf++) {
            int r0 = wm * 64 + mf * 16 + (lane >> 2);
#pragma unroll
            for (int nf = 0; nf < 2; nf++) {
                int col = wn * 16 + nf * 8 + ((lane & 3) << 1);
#pragma unroll
                for (int half_i = 0; half_i < 2; half_i++) {
                    int a = r0 + half_i * 8;
                    int b = a >> 4, h = a & 15;
                    __half* dst = g_ws + ((size_t)b * T_LEN + t) * EMBED
                                  + h * HDIM + col;
                    *(__half2*)dst = __floats2half2_rn(o[mf][nf][2 * half_i],
                                                       o[mf][nf][2 * half_i + 1]);
                }
            }
        }
    }
}

// ---------------------------------------------------------------------------
extern "C" void kernel_launch(void* const* d_in, const int* in_sizes, int n_in,
                              void* d_out, int out_size)
{
    const float* query = (const float*)d_in[0];
    // d_in[1] = key, d_in[2] = value: unused by the reference math
    const float* w_qkv = (const float*)d_in[3];
    const float* b_qkv = (const float*)d_in[4];
    const float* w_out = (const float*)d_in[5];
    const float* b_out = (const float*)d_in[6];
    float* out = (float*)d_out;

    cudaFuncSetAttribute(attn_kernel,
                         cudaFuncAttributeMaxDynamicSharedMemorySize, ATTN_SMEM);
    cudaFuncSetAttribute(gemm_f16_kernel,
                         cudaFuncAttributeMaxDynamicSharedMemorySize, GEMM_SMEM);

    float* qkv_ptr;
    __half *ws_ptr, *qh_ptr, *wqkv_ptr, *wout_ptr;
    cudaGetSymbolAddress((void**)&qkv_ptr, g_qkv);
    cudaGetSymbolAddress((void**)&ws_ptr, g_ws);
    cudaGetSymbolAddress((void**)&qh_ptr, g_qh);
    cudaGetSymbolAddress((void**)&wqkv_ptr, g_wqkv);
    cudaGetSymbolAddress((void**)&wout_ptr, g_wout);

    // Convert fp16 GEMM operands (round-to-nearest).
    {
        int n4q = (MROWS * EMBED) / 4;
        to_half_kernel<<<(n4q + 255) / 256, 256>>>(query, qh_ptr, n4q);
        int n4w = (NQKV * EMBED) / 4;
        to_half_kernel<<<(n4w + 255) / 256, 256>>>(w_qkv, wqkv_ptr, n4w);
        int n4o = (EMBED * EMBED) / 4;
        to_half_kernel<<<(n4o + 255) / 256, 256>>>(w_out, wout_ptr, n4o);
    }

    // QKV GEMM: [16384,1024] @ [3072,1024]^T -> g_qkv (fp32)
    gemm_f16_kernel<<<dim3(NQKV / 128, MROWS / 128), 256, GEMM_SMEM>>>(
        qh_ptr, wqkv_ptr, b_qkv, qkv_ptr, NQKV, EMBED);
    // fused per-t tensor-core attention -> g_ws [B,T,E] (fp16)
    attn_kernel<<<T_LEN, 256, ATTN_SMEM>>>();
    // out GEMM: [16384,1024] @ [1024,1024]^T -> out (fp32)
    gemm_f16_kernel<<<dim3(EMBED / 128, MROWS / 128), 256, GEMM_SMEM>>>(
        ws_ptr, wout_ptr, b_out, out, EMBED, EMBED);
}

// round 14
// speedup vs baseline: 3.4393x; 1.1990x over previous
#include <cuda_runtime.h>
#include <cuda_fp16.h>
#include <cstdint>

#define T_LEN 2048
#define BATCH 8
#define EMBED 1024
#define NHEADS 16
#define HDIM 64
#define BH 128            // BATCH * NHEADS
#define MROWS 16384       // T_LEN * BATCH
#define NQKV 3072         // 3 * EMBED

#define BK 64             // k halves per tile (128B rows)
#define TLD 72            // smem leading dim (halves): 64 + 8 pad, conflict-free
#define STAGES 3
#define TILEH (128 * TLD) // halves per operand tile
#define GEMM_SMEM (STAGES * 2 * TILEH * 2)   // 110592 B; x2 CTAs = 221KB/SM

// attention smem layout (bytes) -- no fp32 S buffer; 94 KB -> 2 CTAs/SM
#define QH_LD 72
#define VT_LD 136
#define PH_LD 136
#define OFF_QH   0
#define OFF_KH   (OFF_QH + BH * QH_LD * 2)          // 18432
#define OFF_VT   (OFF_KH + BH * QH_LD * 2)          // 36864
#define OFF_PH   (OFF_VT + HDIM * VT_LD * 2)        // 54272
#define OFF_IQ   (OFF_PH + BH * PH_LD * 2)          // 89088
#define OFF_IK   (OFF_IQ + BH * 4)
#define OFF_RMAX (OFF_IK + BH * 4)                  // 4 x 128 floats
#define OFF_RSUM (OFF_RMAX + 4 * BH * 4)
#define ATTN_SMEM (OFF_RSUM + 4 * BH * 4)           // 94208

// Scratch (allowed: __device__ globals, no dynamic allocation)
__device__ float  g_qkv[(size_t)MROWS * NQKV];    // [T*B, 3E] fp32
__device__ __half g_ws[(size_t)MROWS * EMBED];    // [B, T, E] fp16
__device__ __half g_qh[(size_t)MROWS * EMBED];    // query fp16
__device__ __half g_wqkv[(size_t)NQKV * EMBED];   // w_qkv fp16
__device__ __half g_wout[(size_t)EMBED * EMBED];  // w_out fp16

#define LDM_X4(r0, r1, r2, r3, p) \
    asm volatile("ldmatrix.sync.aligned.m8n8.x4.b16 {%0,%1,%2,%3}, [%4];\n" \
                 : "=r"(r0), "=r"(r1), "=r"(r2), "=r"(r3) \
                 : "r"((uint32_t)__cvta_generic_to_shared(p)))

#define MMA_F16(c, af, b0, b1) \
    asm volatile("mma.sync.aligned.m16n8k16.row.col.f32.f16.f16.f32 " \
                 "{%0,%1,%2,%3}, {%4,%5,%6,%7}, {%8,%9}, {%0,%1,%2,%3};\n" \
                 : "+f"((c)[0]), "+f"((c)[1]), "+f"((c)[2]), "+f"((c)[3]) \
                 : "r"((af)[0]), "r"((af)[1]), "r"((af)[2]), "r"((af)[3]), \
                   "r"(b0), "r"(b1))

// ---------------------------------------------------------------------------
// Elementwise fp32 -> fp16 conversion, float4-vectorized.
// ---------------------------------------------------------------------------
__global__ __launch_bounds__(256) void to_half_kernel(
    const float* __restrict__ x, __half* __restrict__ y, int n4)
{
    int i = blockIdx.x * blockDim.x + threadIdx.x;
    if (i < n4) {
        float4 v = ((const float4*)x)[i];
        __half2* y2 = (__half2*)y;
        y2[2 * i]     = __floats2half2_rn(v.x, v.y);
        y2[2 * i + 1] = __floats2half2_rn(v.z, v.w);
    }
}

// ---------------------------------------------------------------------------
// fp16 tensor-core GEMM (fp32 accumulate): C[m][n] = sum_k A[m][k]*B[n][k]+bias[n]
// 128x128 tile, BK=64 halves, 256 threads, 8 warps (2x4), warp tile 64x32.
// (unchanged from validated R13 kernel)
// ---------------------------------------------------------------------------
__global__ __launch_bounds__(256, 2) void gemm_f16_kernel(
    const __half* __restrict__ A, const __half* __restrict__ B,
    const float* __restrict__ bias, float* __restrict__ C,
    int N, int K)
{
    extern __shared__ __half smh[];
    const int tid  = threadIdx.x;
    const int lane = tid & 31;
    const int warp = tid >> 5;
    const int wm   = warp >> 2;
    const int wn   = warp & 3;
    const int bm   = blockIdx.y << 7;
    const int bn   = blockIdx.x << 7;

    const int lrow   = tid >> 3;
    const int lchunk = tid & 7;
    const __half* gA = A + (size_t)(bm + lrow) * K + lchunk * 8;
    const __half* gB = B + (size_t)(bn + lrow) * K + lchunk * 8;

    const int a_row  = wm * 64 + (lane & 15);
    const int a_koff = (lane >> 4) * 8;
    const int b_row  = wn * 32 + ((lane >> 4) & 1) * 8 + (lane & 7);
    const int b_koff = ((lane >> 3) & 1) * 8;

    float c[4][4][4];
#pragma unroll
    for (int mf = 0; mf < 4; mf++)
#pragma unroll
        for (int nf = 0; nf < 4; nf++)
#pragma unroll
            for (int r = 0; r < 4; r++) c[mf][nf][r] = 0.0f;

    const int ntiles = K >> 6;

#define LOAD_TILE(s, k0) do {                                                  \
    __half* As_ = smh + (s) * (2 * TILEH);                                     \
    __half* Bs_ = As_ + TILEH;                                                 \
    _Pragma("unroll")                                                          \
    for (int i_ = 0; i_ < 4; i_++) {                                           \
        uint32_t sa_ = (uint32_t)__cvta_generic_to_shared(                     \
            As_ + (lrow + i_ * 32) * TLD + lchunk * 8);                        \
        asm volatile("cp.async.cg.shared.global [%0], [%1], 16;\n"             \
                     :: "r"(sa_), "l"(gA + (size_t)(i_ * 32) * K + (k0)));     \
        uint32_t sb_ = (uint32_t)__cvta_generic_to_shared(                     \
            Bs_ + (lrow + i_ * 32) * TLD + lchunk * 8);                        \
        asm volatile("cp.async.cg.shared.global [%0], [%1], 16;\n"             \
                     :: "r"(sb_), "l"(gB + (size_t)(i_ * 32) * K + (k0)));     \
    }                                                                          \
} while (0)

#pragma unroll
    for (int s = 0; s < STAGES - 1; s++) {
        LOAD_TILE(s, s * BK);
        asm volatile("cp.async.commit_group;\n");
    }

    for (int kt = 0; kt < ntiles; kt++) {
        asm volatile("cp.async.wait_group %0;\n" :: "n"(STAGES - 2));
        __syncthreads();

        int pf = kt + STAGES - 1;
        if (pf < ntiles) LOAD_TILE(pf % STAGES, pf * BK);
        asm volatile("cp.async.commit_group;\n");

        const __half* As = smh + (kt % STAGES) * (2 * TILEH);
        const __half* Bs = As + TILEH;

#pragma unroll
        for (int ks = 0; ks < 4; ks++) {
            uint32_t afr[4][4];
#pragma unroll
            for (int mf = 0; mf < 4; mf++)
                LDM_X4(afr[mf][0], afr[mf][1], afr[mf][2], afr[mf][3],
                       As + (a_row + mf * 16) * TLD + ks * 16 + a_koff);
            uint32_t bfr[4][2];
#pragma unroll
            for (int bi = 0; bi < 2; bi++)
                LDM_X4(bfr[2 * bi][0], bfr[2 * bi][1],
                       bfr[2 * bi + 1][0], bfr[2 * bi + 1][1],
                       Bs + (b_row + bi * 16) * TLD + ks * 16 + b_koff);
#pragma unroll
            for (int mf = 0; mf < 4; mf++)
#pragma unroll
                for (int nf = 0; nf < 4; nf++)
                    MMA_F16(c[mf][nf], afr[mf], bfr[nf][0], bfr[nf][1]);
        }
    }

#pragma unroll
    for (int mf = 0; mf < 4; mf++) {
        int r0 = bm + wm * 64 + mf * 16 + (lane >> 2);
#pragma unroll
        for (int nf = 0; nf < 4; nf++) {
            int col = bn + wn * 32 + nf * 8 + ((lane & 3) << 1);
            float2 bv = *(const float2*)(bias + col);
            float2 o0 = make_float2(c[mf][nf][0] + bv.x, c[mf][nf][1] + bv.y);
            float2 o1 = make_float2(c[mf][nf][2] + bv.x, c[mf][nf][3] + bv.y);
            *(float2*)(C + (size_t)r0 * N + col) = o0;
            *(float2*)(C + (size_t)(r0 + 8) * N + col) = o1;
        }
    }
#undef LOAD_TILE
}

// ---------------------------------------------------------------------------
// Per-t tensor-core attention, register-resident softmax.
// S stays in mma fragments; row max/sum via shfl + 2KB cross-warp buffers;
// ph holds UNNORMALIZED exp(s-max) fp16; 1/sum folded into PV epilogue.
// 94 KB smem -> 2 CTAs/SM.
// ---------------------------------------------------------------------------
__global__ __launch_bounds__(256, 2) void attn_kernel()
{
    extern __shared__ char smem[];
    __half* qh   = (__half*)(smem + OFF_QH);   // 128 x 72
    __half* kh   = (__half*)(smem + OFF_KH);   // 128 x 72
    __half* vt   = (__half*)(smem + OFF_VT);   // 64 x 136 (transposed: [d][j])
    __half* ph   = (__half*)(smem + OFF_PH);   // 128 x 136 (exp values)
    float*  invq = (float*)(smem + OFF_IQ);    // 128
    float*  invk = (float*)(smem + OFF_IK);    // 128
    float*  rmax = (float*)(smem + OFF_RMAX);  // [4][128] per-wn row maxima
    float*  rsum = (float*)(smem + OFF_RSUM);  // [4][128] per-wn row sums

    const int t = blockIdx.x;
    const int tid = threadIdx.x;
    const int lane = tid & 31;
    const int warp = tid >> 5;
    const int wm = warp >> 2;      // 0..1
    const int wn = warp & 3;       // 0..3

    // Load q,k,v (fp32) -> fp16 tiles; v stored transposed vt[d][j]
    for (int idx = tid; idx < BH * (HDIM / 4); idx += 256) {
        int a  = idx >> 4;
        int d4 = (idx & 15) << 2;
        int b = a >> 4, h = a & 15;
        const float* base = g_qkv + (size_t)(t * BATCH + b) * NQKV + h * HDIM + d4;
        float4 qv = *(const float4*)(base);
        float4 kv = *(const float4*)(base + EMBED);
        float4 vv = *(const float4*)(base + 2 * EMBED);
        __half2* qd = (__half2*)(qh + a * QH_LD + d4);
        qd[0] = __floats2half2_rn(qv.x, qv.y);
        qd[1] = __floats2half2_rn(qv.z, qv.w);
        __half2* kd = (__half2*)(kh + a * QH_LD + d4);
        kd[0] = __floats2half2_rn(kv.x, kv.y);
        kd[1] = __floats2half2_rn(kv.z, kv.w);
        vt[(d4 + 0) * VT_LD + a] = __float2half_rn(vv.x);
        vt[(d4 + 1) * VT_LD + a] = __float2half_rn(vv.y);
        vt[(d4 + 2) * VT_LD + a] = __float2half_rn(vv.z);
        vt[(d4 + 3) * VT_LD + a] = __float2half_rn(vv.w);
    }
    __syncthreads();

    // Row norms over fp16 values
    {
        const __half2* r = (const __half2*)((tid < BH ? qh : kh)
                            + (tid & 127) * QH_LD);
        float s = 0.0f;
#pragma unroll
        for (int d = 0; d < HDIM / 2; d++) {
            float2 f = __half22float2(r[d]);
            s = fmaf(f.x, f.x, fmaf(f.y, f.y, s));
        }
        float inv = rsqrtf(s);
        if (tid < BH) invq[tid] = inv; else invk[tid - BH] = inv;
    }
    __syncthreads();

    const int a_row  = wm * 64 + (lane & 15);
    const int a_koff = (lane >> 4) * 8;

    // S = qh @ kh^T (fp32 accum), scale in registers
    float c[4][4][4];
    {
        const int b_row  = wn * 32 + ((lane >> 4) & 1) * 8 + (lane & 7);
        const int b_koff = ((lane >> 3) & 1) * 8;
#pragma unroll
        for (int mf = 0; mf < 4; mf++)
#pragma unroll
            for (int nf = 0; nf < 4; nf++)
#pragma unroll
                for (int r = 0; r < 4; r++) c[mf][nf][r] = 0.0f;

#pragma unroll
        for (int ks = 0; ks < 4; ks++) {           // K = 64 = 4 x 16
            uint32_t afr[4][4];
#pragma unroll
            for (int mf = 0; mf < 4; mf++)
                LDM_X4(afr[mf][0], afr[mf][1], afr[mf][2], afr[mf][3],
                       qh + (a_row + mf * 16) * QH_LD + ks * 16 + a_koff);
            uint32_t bfr[4][2];
#pragma unroll
            for (int bi = 0; bi < 2; bi++)
                LDM_X4(bfr[2 * bi][0], bfr[2 * bi][1],
                       bfr[2 * bi + 1][0], bfr[2 * bi + 1][1],
                       kh + (b_row + bi * 16) * QH_LD + ks * 16 + b_koff);
#pragma unroll
            for (int mf = 0; mf < 4; mf++)
#pragma unroll
                for (int nf = 0; nf < 4; nf++)
                    MMA_F16(c[mf][nf], afr[mf], bfr[nf][0], bfr[nf][1]);
        }
    }

    // Scale by invq*invk/8 and compute per-warp row maxima (shfl within
    // 4-lane row groups), publish to rmax[wn][row].
#pragma unroll
    for (int mf = 0; mf < 4; mf++) {
        int r0 = wm * 64 + mf * 16 + (lane >> 2);
        float s0 = invq[r0] * 0.125f;
        float s1 = invq[r0 + 8] * 0.125f;
        float m0 = -1e30f, m1 = -1e30f;
#pragma unroll
        for (int nf = 0; nf < 4; nf++) {
            int col = wn * 32 + nf * 8 + ((lane & 3) << 1);
            float k0 = invk[col], k1 = invk[col + 1];
            c[mf][nf][0] *= s0 * k0; c[mf][nf][1] *= s0 * k1;
            c[mf][nf][2] *= s1 * k0; c[mf][nf][3] *= s1 * k1;
            m0 = fmaxf(m0, fmaxf(c[mf][nf][0], c[mf][nf][1]));
            m1 = fmaxf(m1, fmaxf(c[mf][nf][2], c[mf][nf][3]));
        }
        m0 = fmaxf(m0, __shfl_xor_sync(0xffffffffu, m0, 1));
        m0 = fmaxf(m0, __shfl_xor_sync(0xffffffffu, m0, 2));
        m1 = fmaxf(m1, __shfl_xor_sync(0xffffffffu, m1, 1));
        m1 = fmaxf(m1, __shfl_xor_sync(0xffffffffu, m1, 2));
        if ((lane & 3) == 0) {
            rmax[wn * BH + r0]     = m0;
            rmax[wn * BH + r0 + 8] = m1;
        }
    }
    __syncthreads();

    // exp(s - rowmax), write fp16 to ph, publish per-warp row sums.
#pragma unroll
    for (int mf = 0; mf < 4; mf++) {
        int r0 = wm * 64 + mf * 16 + (lane >> 2);
        float M0 = fmaxf(fmaxf(rmax[r0], rmax[BH + r0]),
                         fmaxf(rmax[2 * BH + r0], rmax[3 * BH + r0]));
        float M1 = fmaxf(fmaxf(rmax[r0 + 8], rmax[BH + r0 + 8]),
                         fmaxf(rmax[2 * BH + r0 + 8], rmax[3 * BH + r0 + 8]));
        float sum0 = 0.0f, sum1 = 0.0f;
#pragma unroll
        for (int nf = 0; nf < 4; nf++) {
            int col = wn * 32 + nf * 8 + ((lane & 3) << 1);
            float e0 = __expf(c[mf][nf][0] - M0);
            float e1 = __expf(c[mf][nf][1] - M0);
            float e2 = __expf(c[mf][nf][2] - M1);
            float e3 = __expf(c[mf][nf][3] - M1);
            sum0 += e0 + e1; sum1 += e2 + e3;
            *(__half2*)(ph + r0 * PH_LD + col)       = __floats2half2_rn(e0, e1);
            *(__half2*)(ph + (r0 + 8) * PH_LD + col) = __floats2half2_rn(e2, e3);
        }
        sum0 += __shfl_xor_sync(0xffffffffu, sum0, 1);
        sum0 += __shfl_xor_sync(0xffffffffu, sum0, 2);
        sum1 += __shfl_xor_sync(0xffffffffu, sum1, 1);
        sum1 += __shfl_xor_sync(0xffffffffu, sum1, 2);
        if ((lane & 3) == 0) {
            rsum[wn * BH + r0]     = sum0;
            rsum[wn * BH + r0 + 8] = sum1;
        }
    }
    __syncthreads();

    // Row normalizers (kept in registers through PV)
    float rinv0[4], rinv1[4];
#pragma unroll
    for (int mf = 0; mf < 4; mf++) {
        int r0 = wm * 64 + mf * 16 + (lane >> 2);
        rinv0[mf] = 1.0f / (rsum[r0] + rsum[BH + r0]
                            + rsum[2 * BH + r0] + rsum[3 * BH + r0]);
        rinv1[mf] = 1.0f / (rsum[r0 + 8] + rsum[BH + r0 + 8]
                            + rsum[2 * BH + r0 + 8] + rsum[3 * BH + r0 + 8]);
    }

    // ws = (1/sum) * E @ V : A = ph [128x128], B = vt [64(d) x 128(j)]
    {
        const int b_row  = wn * 16 + ((lane >> 4) & 1) * 8 + (lane & 7);
        const int b_koff = ((lane >> 3) & 1) * 8;

        float o[4][2][4];
#pragma unroll
        for (int mf = 0; mf < 4; mf++)
#pragma unroll
            for (int nf = 0; nf < 2; nf++)
#pragma unroll
                for (int r = 0; r < 4; r++) o[mf][nf][r] = 0.0f;

#pragma unroll
        for (int ks = 0; ks < 8; ks++) {           // K = 128 = 8 x 16
            uint32_t afr[4][4];
#pragma unroll
            for (int mf = 0; mf < 4; mf++)
                LDM_X4(afr[mf][0], afr[mf][1], afr[mf][2], afr[mf][3],
                       ph + (a_row + mf * 16) * PH_LD + ks * 16 + a_koff);
            uint32_t bfr[2][2];
            LDM_X4(bfr[0][0], bfr[0][1], bfr[1][0], bfr[1][1],
                   vt + b_row * VT_LD + ks * 16 + b_koff);
#pragma unroll
            for (int mf = 0; mf < 4; mf++)
#pragma unroll
                for (int nf = 0; nf < 2; nf++)
                    MMA_F16(o[mf][nf], afr[mf], bfr[nf][0], bfr[nf][1]);
        }

        // store fp16 to g_ws [B, T, E] with row normalization
#pragma unroll
        for (int mf = 0; mf < 4; mf++) {
            int r0 = wm * 64 + mf * 16 + (lane >> 2);
#pragma unroll
            for (int nf = 0; nf < 2; nf++) {
                int col = wn * 16 + nf * 8 + ((lane & 3) << 1);
#pragma unroll
                for (int half_i = 0; half_i < 2; half_i++) {
                    int a = r0 + half_i * 8;
                    int b = a >> 4, h = a & 15;
                    float rv = half_i ? rinv1[mf] : rinv0[mf];
                    __half* dst = g_ws + ((size_t)b * T_LEN + t) * EMBED
                                  + h * HDIM + col;
                    *(__half2*)dst = __floats2half2_rn(
                        o[mf][nf][2 * half_i] * rv,
                        o[mf][nf][2 * half_i + 1] * rv);
                }
            }
        }
    }
}

// ---------------------------------------------------------------------------
extern "C" void kernel_launch(void* const* d_in, const int* in_sizes, int n_in,
                              void* d_out, int out_size)
{
    const float* query = (const float*)d_in[0];
    // d_in[1] = key, d_in[2] = value: unused by the reference math
    const float* w_qkv = (const float*)d_in[3];
    const float* b_qkv = (const float*)d_in[4];
    const float* w_out = (const float*)d_in[5];
    const float* b_out = (const float*)d_in[6];
    float* out = (float*)d_out;

    cudaFuncSetAttribute(attn_kernel,
                         cudaFuncAttributeMaxDynamicSharedMemorySize, ATTN_SMEM);
    cudaFuncSetAttribute(gemm_f16_kernel,
                         cudaFuncAttributeMaxDynamicSharedMemorySize, GEMM_SMEM);

    float* qkv_ptr;
    __half *ws_ptr, *qh_ptr, *wqkv_ptr, *wout_ptr;
    cudaGetSymbolAddress((void**)&qkv_ptr, g_qkv);
    cudaGetSymbolAddress((void**)&ws_ptr, g_ws);
    cudaGetSymbolAddress((void**)&qh_ptr, g_qh);
    cudaGetSymbolAddress((void**)&wqkv_ptr, g_wqkv);
    cudaGetSymbolAddress((void**)&wout_ptr, g_wout);

    // Convert fp16 GEMM operands (round-to-nearest).
    {
        int n4q = (MROWS * EMBED) / 4;
        to_half_kernel<<<(n4q + 255) / 256, 256>>>(query, qh_ptr, n4q);
        int n4w = (NQKV * EMBED) / 4;
        to_half_kernel<<<(n4w + 255) / 256, 256>>>(w_qkv, wqkv_ptr, n4w);
        int n4o = (EMBED * EMBED) / 4;
        to_half_kernel<<<(n4o + 255) / 256, 256>>>(w_out, wout_ptr, n4o);
    }

    // QKV GEMM: [16384,1024] @ [3072,1024]^T -> g_qkv (fp32)
    gemm_f16_kernel<<<dim3(NQKV / 128, MROWS / 128), 256, GEMM_SMEM>>>(
        qh_ptr, wqkv_ptr, b_qkv, qkv_ptr, NQKV, EMBED);
    // fused per-t tensor-core attention -> g_ws [B,T,E] (fp16)
    attn_kernel<<<T_LEN, 256, ATTN_SMEM>>>();
    // out GEMM: [16384,1024] @ [1024,1024]^T -> out (fp32)
    gemm_f16_kernel<<<dim3(EMBED / 128, MROWS / 128), 256, GEMM_SMEM>>>(
        ws_ptr, wout_ptr, b_out, out, EMBED, EMBED);
}